// round 5
// baseline (speedup 1.0000x reference)
#include <cuda_runtime.h>
#include <cuda_fp16.h>
#include <cuda_bf16.h>
#include <cstdint>

#define NN 50000
#define EE 800000
#define RR 3
#define DD 128
#define HH 4
#define MSEG (RR * NN)
#define SCAN_BLK 1024
#define NSB ((MSEG + SCAN_BLK - 1) / SCAN_BLK)   // 147

// ---------------- scratch (device globals) --------------------------------------
__device__ __align__(16) __half g_hh[(size_t)RR * NN * DD];
__device__ float g_asrc[RR * NN * HH];
__device__ float g_adst[RR * NN * HH];
__device__ float g_acc[(size_t)NN * DD];
__device__ float g_gw[RR];
__device__ float g_biasf[DD];
__device__ int   g_cnt[MSEG];
__device__ int   g_off[MSEG];
__device__ int   g_cur[MSEG];
__device__ int   g_bsum[256];
__device__ int   g_esrc[RR * EE];

// ---------------- K0: gate softmax + fused bias ---------------------------------
__global__ void k_prep(const float* __restrict__ gate,
                       const float* __restrict__ bias,
                       float* __restrict__ out_gw) {
    __shared__ float gw[RR];
    int d = threadIdx.x;  // 128
    if (d == 0) {
        float m = gate[0];
        for (int r = 1; r < RR; r++) m = fmaxf(m, gate[r]);
        float e[RR], s = 0.f;
        for (int r = 0; r < RR; r++) { e[r] = expf(gate[r] - m); s += e[r]; }
        for (int r = 0; r < RR; r++) {
            gw[r] = e[r] / s;
            g_gw[r] = gw[r];
            out_gw[r] = gw[r];
        }
    }
    __syncthreads();
    float b = 0.f;
    for (int r = 0; r < RR; r++) b += gw[r] * bias[r * DD + d];
    g_biasf[d] = b;
}

// ---------------- K1: init acc = x + fused_bias ; zero degree counts ------------
__global__ void k_init(const float* __restrict__ x) {
    int i = blockIdx.x * blockDim.x + threadIdx.x;
    const int ACC4 = NN * DD / 4;
    const int CNT4 = MSEG / 4;
    if (i < ACC4) {
        float4 xv = ((const float4*)x)[i];
        int d4 = (i & 31) * 4;
        float4 bf = *(const float4*)&g_biasf[d4];
        float4 o;
        o.x = xv.x + bf.x; o.y = xv.y + bf.y;
        o.z = xv.z + bf.z; o.w = xv.w + bf.w;
        ((float4*)g_acc)[i] = o;
    } else {
        int j = i - ACC4;
        if (j < CNT4) ((int4*)g_cnt)[j] = make_int4(0, 0, 0, 0);
    }
}

// ---------------- K2: bf16x3 mma.sync GEMM + fused alpha epilogue ----------------
#define LDA 136                    // padded row stride in halfs (bank-conflict-free)

__device__ __forceinline__ void mma_bf16(float* c, const uint32_t* a, const uint32_t* b) {
    asm volatile(
        "mma.sync.aligned.m16n8k16.row.col.f32.bf16.bf16.f32 "
        "{%0,%1,%2,%3}, {%4,%5,%6,%7}, {%8,%9}, {%0,%1,%2,%3};"
        : "+f"(c[0]), "+f"(c[1]), "+f"(c[2]), "+f"(c[3])
        : "r"(a[0]), "r"(a[1]), "r"(a[2]), "r"(a[3]), "r"(b[0]), "r"(b[1]));
}

__device__ __forceinline__ void split_bf16(float f, unsigned short& h, unsigned short& l) {
    __nv_bfloat16 bh = __float2bfloat16(f);
    float fh = __bfloat162float(bh);
    __nv_bfloat16 bl = __float2bfloat16(f - fh);
    h = *(unsigned short*)&bh;
    l = *(unsigned short*)&bl;
}

__global__ void __launch_bounds__(256, 1)
k_gemm(const float* __restrict__ x, const float* __restrict__ W,
       const float* __restrict__ att_src, const float* __restrict__ att_dst) {
    extern __shared__ __align__(16) unsigned short sm[];
    unsigned short* As_hi = sm;                       // 128 x LDA
    unsigned short* As_lo = As_hi + 128 * LDA;
    unsigned short* Bs_hi = As_lo + 128 * LDA;        // [n][k]
    unsigned short* Bs_lo = Bs_hi + 128 * LDA;
    float* as_s = (float*)(Bs_lo + 128 * LDA);
    float* ad_s = as_s + DD;
    __half* Hs = (__half*)As_hi;                      // reused after mainloop

    const int r = blockIdx.y;
    const int row0 = blockIdx.x * 128;
    const int tid = threadIdx.x;
    const int warp = tid >> 5, lane = tid & 31;
    const int g = lane >> 2, tg = lane & 3;
    const int wm = warp >> 1, wn = warp & 1;          // 4x2 warp grid
    const float* Wr = W + (size_t)r * DD * DD;

    if (tid < DD) {
        as_s[tid] = __ldg(&att_src[r * DD + tid]);
        ad_s[tid] = __ldg(&att_dst[r * DD + tid]);
    }

    // ---- load & split x tile (128 x 128) ----
#pragma unroll
    for (int i = 0; i < 16; i++) {
        int idx = i * 256 + tid;                      // 4096 float4
        int row = idx >> 5, c4 = (idx & 31) * 4;
        int grow = row0 + row;
        float4 v = make_float4(0.f, 0.f, 0.f, 0.f);
        if (grow < NN) v = __ldg((const float4*)&x[(size_t)grow * DD + c4]);
        float f[4] = {v.x, v.y, v.z, v.w};
        unsigned short h[4], l[4];
#pragma unroll
        for (int j = 0; j < 4; j++) split_bf16(f[j], h[j], l[j]);
        *(uint2*)&As_hi[row * LDA + c4] = make_uint2(h[0] | (h[1] << 16), h[2] | (h[3] << 16));
        *(uint2*)&As_lo[row * LDA + c4] = make_uint2(l[0] | (l[1] << 16), l[2] | (l[3] << 16));
    }
    // ---- load & split W, transposed into Bs[n][k] ----
#pragma unroll
    for (int i = 0; i < 16; i++) {
        int idx = i * 256 + tid;
        int k = idx >> 5, n4 = (idx & 31) * 4;
        float4 v = __ldg((const float4*)&Wr[(size_t)k * DD + n4]);
        float f[4] = {v.x, v.y, v.z, v.w};
#pragma unroll
        for (int j = 0; j < 4; j++) {
            unsigned short h, l;
            split_bf16(f[j], h, l);
            Bs_hi[(n4 + j) * LDA + k] = h;
            Bs_lo[(n4 + j) * LDA + k] = l;
        }
    }
    __syncthreads();

    // ---- mainloop: warp tile 32 (rows) x 64 (cols) ----
    float c[2][8][4];
#pragma unroll
    for (int mt = 0; mt < 2; mt++)
#pragma unroll
        for (int nt = 0; nt < 8; nt++)
#pragma unroll
            for (int q = 0; q < 4; q++) c[mt][nt][q] = 0.f;

#pragma unroll 2
    for (int ks = 0; ks < 8; ks++) {
        uint32_t ahi[2][4], alo[2][4];
#pragma unroll
        for (int mt = 0; mt < 2; mt++) {
            int m = wm * 32 + mt * 16 + g;
            int ko = ks * 16 + 2 * tg;
            const unsigned short* ph = &As_hi[m * LDA + ko];
            const unsigned short* pl = &As_lo[m * LDA + ko];
            ahi[mt][0] = *(const uint32_t*)ph;
            ahi[mt][1] = *(const uint32_t*)(ph + 8 * LDA);
            ahi[mt][2] = *(const uint32_t*)(ph + 8);
            ahi[mt][3] = *(const uint32_t*)(ph + 8 * LDA + 8);
            alo[mt][0] = *(const uint32_t*)pl;
            alo[mt][1] = *(const uint32_t*)(pl + 8 * LDA);
            alo[mt][2] = *(const uint32_t*)(pl + 8);
            alo[mt][3] = *(const uint32_t*)(pl + 8 * LDA + 8);
        }
#pragma unroll
        for (int nt = 0; nt < 8; nt++) {
            int n = wn * 64 + nt * 8 + g;
            int ko = ks * 16 + 2 * tg;
            const unsigned short* ph = &Bs_hi[n * LDA + ko];
            const unsigned short* pl = &Bs_lo[n * LDA + ko];
            uint32_t bhi[2], blo[2];
            bhi[0] = *(const uint32_t*)ph;
            bhi[1] = *(const uint32_t*)(ph + 8);
            blo[0] = *(const uint32_t*)pl;
            blo[1] = *(const uint32_t*)(pl + 8);
#pragma unroll
            for (int mt = 0; mt < 2; mt++) {
                mma_bf16(c[mt][nt], ahi[mt], bhi);
                mma_bf16(c[mt][nt], ahi[mt], blo);
                mma_bf16(c[mt][nt], alo[mt], bhi);
            }
        }
    }

    // ---- alpha dots from exact fp32 accumulators ----
    float ps[4][2], pd[4][2];   // [mt*2 + rowhalf][head-in-warp]
#pragma unroll
    for (int s = 0; s < 4; s++) { ps[s][0] = ps[s][1] = pd[s][0] = pd[s][1] = 0.f; }
#pragma unroll
    for (int mt = 0; mt < 2; mt++)
#pragma unroll
        for (int nt = 0; nt < 8; nt++) {
            int col = wn * 64 + nt * 8 + 2 * tg;
            float2 a2 = *(float2*)&as_s[col];
            float2 d2 = *(float2*)&ad_s[col];
            int hh = nt >> 2;
            ps[mt * 2 + 0][hh] += c[mt][nt][0] * a2.x + c[mt][nt][1] * a2.y;
            pd[mt * 2 + 0][hh] += c[mt][nt][0] * d2.x + c[mt][nt][1] * d2.y;
            ps[mt * 2 + 1][hh] += c[mt][nt][2] * a2.x + c[mt][nt][3] * a2.y;
            pd[mt * 2 + 1][hh] += c[mt][nt][2] * d2.x + c[mt][nt][3] * d2.y;
        }
#pragma unroll
    for (int o = 1; o <= 2; o <<= 1)
#pragma unroll
        for (int s = 0; s < 4; s++)
#pragma unroll
            for (int hh = 0; hh < 2; hh++) {
                ps[s][hh] += __shfl_xor_sync(0xffffffffu, ps[s][hh], o);
                pd[s][hh] += __shfl_xor_sync(0xffffffffu, pd[s][hh], o);
            }
    if (tg == 0) {
#pragma unroll
        for (int s = 0; s < 4; s++) {
            int row = row0 + wm * 32 + (s >> 1) * 16 + (s & 1) * 8 + g;
            if (row < NN) {
#pragma unroll
                for (int hh = 0; hh < 2; hh++) {
                    int head = wn * 2 + hh;
                    g_asrc[((size_t)r * NN + row) * HH + head] = ps[s][hh];
                    g_adst[((size_t)r * NN + row) * HH + head] = pd[s][hh];
                }
            }
        }
    }

    // ---- stage fp16 h through smem, then coalesced global store ----
    __syncthreads();   // everyone done reading As before overwrite
#pragma unroll
    for (int mt = 0; mt < 2; mt++)
#pragma unroll
        for (int nt = 0; nt < 8; nt++) {
            int row = wm * 32 + mt * 16 + g;
            int col = wn * 64 + nt * 8 + 2 * tg;
            *(__half2*)&Hs[row * LDA + col] = __floats2half2_rn(c[mt][nt][0], c[mt][nt][1]);
            *(__half2*)&Hs[(row + 8) * LDA + col] = __floats2half2_rn(c[mt][nt][2], c[mt][nt][3]);
        }
    __syncthreads();
#pragma unroll
    for (int i = 0; i < 8; i++) {
        int idx = i * 256 + tid;              // 2048 uint4 = 128 rows x 16
        int row = idx >> 4, q = idx & 15;
        int grow = row0 + row;
        if (grow < NN) {
            uint4 v = *(uint4*)&Hs[row * LDA + q * 8];
            *(uint4*)&g_hh[((size_t)r * NN + grow) * DD + q * 8] = v;
        }
    }
}

// ---------------- K4a: degree histogram (4 edges/thread) -------------------------
__global__ void k_hist(const int* __restrict__ ei) {
    int i = blockIdx.x * blockDim.x + threadIdx.x;
    int r = blockIdx.y;
    if (i >= EE / 4) return;
    int4 d = __ldg((const int4*)(ei + r * 2 * EE + EE) + i);
    atomicAdd(&g_cnt[r * NN + d.x], 1);
    atomicAdd(&g_cnt[r * NN + d.y], 1);
    atomicAdd(&g_cnt[r * NN + d.z], 1);
    atomicAdd(&g_cnt[r * NN + d.w], 1);
}

// ---------------- K4b/c/d: scan ---------------------------------------------------
__global__ void k_scan_a() {
    __shared__ int ws[8];
    int tid = threadIdx.x;
    int base = blockIdx.x * SCAN_BLK + tid * 4;
    int s = 0;
#pragma unroll
    for (int k = 0; k < 4; k++) {
        int idx = base + k;
        if (idx < MSEG) s += g_cnt[idx];
    }
#pragma unroll
    for (int o = 16; o >= 1; o >>= 1) s += __shfl_xor_sync(0xffffffffu, s, o);
    if ((tid & 31) == 0) ws[tid >> 5] = s;
    __syncthreads();
    if (tid == 0) {
        int t = 0;
        for (int i = 0; i < 8; i++) t += ws[i];
        g_bsum[blockIdx.x] = t;
    }
}
__global__ void k_scan_b() {
    if (threadIdx.x == 0) {
        int run = 0;
        for (int i = 0; i < NSB; i++) { int v = g_bsum[i]; g_bsum[i] = run; run += v; }
    }
}
__global__ void k_scan_c() {
    __shared__ int ws[8];
    int tid = threadIdx.x;
    int lane = tid & 31, warp = tid >> 5;
    int base = blockIdx.x * SCAN_BLK + tid * 4;
    int c[4];
#pragma unroll
    for (int k = 0; k < 4; k++) {
        int idx = base + k;
        c[k] = (idx < MSEG) ? g_cnt[idx] : 0;
    }
    int t = c[0] + c[1] + c[2] + c[3];
    int inc = t;
#pragma unroll
    for (int o = 1; o < 32; o <<= 1) {
        int v = __shfl_up_sync(0xffffffffu, inc, o);
        if (lane >= o) inc += v;
    }
    if (lane == 31) ws[warp] = inc;
    __syncthreads();
    if (tid == 0) {
        int run = 0;
        for (int i = 0; i < 8; i++) { int v = ws[i]; ws[i] = run; run += v; }
    }
    __syncthreads();
    int ex = inc - t + ws[warp] + g_bsum[blockIdx.x];
#pragma unroll
    for (int k = 0; k < 4; k++) {
        int idx = base + k;
        if (idx < MSEG) { g_off[idx] = ex; g_cur[idx] = ex; }
        ex += c[k];
    }
}

// ---------------- K4e: scatter edges into CSR (4 edges/thread) --------------------
__global__ void k_scatter(const int* __restrict__ ei) {
    int i = blockIdx.x * blockDim.x + threadIdx.x;
    int r = blockIdx.y;
    if (i >= EE / 4) return;
    int4 s = __ldg((const int4*)(ei + r * 2 * EE) + i);
    int4 d = __ldg((const int4*)(ei + r * 2 * EE + EE) + i);
    int p;
    p = atomicAdd(&g_cur[r * NN + d.x], 1); g_esrc[p] = s.x;
    p = atomicAdd(&g_cur[r * NN + d.y], 1); g_esrc[p] = s.y;
    p = atomicAdd(&g_cur[r * NN + d.z], 1); g_esrc[p] = s.z;
    p = atomicAdd(&g_cur[r * NN + d.w], 1); g_esrc[p] = s.w;
}

// ---------------- K5: fused softmax + aggregation (warp per (r, dst)) -------------
__global__ void __launch_bounds__(256)
k_agg(int dummy) {
    int wid = (blockIdx.x * blockDim.x + threadIdx.x) >> 5;
    int lane = threadIdx.x & 31;
    if (wid >= MSEG) return;
    int r = wid / NN, n = wid - r * NN;
    int head = lane >> 3;
    int c4 = lane * 4;

    int beg = g_off[wid];
    int end = g_cur[wid];
    if (beg == end) return;

    float adv = g_adst[wid * HH + head];
    float denom = 0.f;
    float4 acc = make_float4(0.f, 0.f, 0.f, 0.f);
    const __half* hr = g_hh + (size_t)r * NN * DD;
    const float* ar = g_asrc + (size_t)r * NN * HH;

#pragma unroll 2
    for (int i = beg; i < end; i++) {
        int src = __ldg(&g_esrc[i]);
        float asv = __ldg(&ar[src * HH + head]);
        float v = asv + adv;
        v = v >= 0.f ? v : 0.2f * v;
        float w = __expf(v);
        denom += w;
        uint2 hv = __ldg((const uint2*)&hr[(size_t)src * DD + c4]);
        float2 f0 = __half22float2(*(__half2*)&hv.x);
        float2 f1 = __half22float2(*(__half2*)&hv.y);
        acc.x += w * f0.x; acc.y += w * f0.y;
        acc.z += w * f1.x; acc.w += w * f1.y;
    }
    float scale = g_gw[r] / (denom + 1e-16f);
    float* op = &g_acc[(size_t)n * DD + c4];
    asm volatile("red.global.add.v4.f32 [%0], {%1,%2,%3,%4};"
                 :: "l"(op), "f"(scale * acc.x), "f"(scale * acc.y),
                    "f"(scale * acc.z), "f"(scale * acc.w) : "memory");
}

// ---------------- K6: LayerNorm + output (warp per node) --------------------------
__global__ void k_ln(const float* __restrict__ gamma,
                     const float* __restrict__ beta,
                     float* __restrict__ out) {
    int wid = (blockIdx.x * blockDim.x + threadIdx.x) >> 5;
    int lane = threadIdx.x & 31;
    if (wid >= NN) return;
    float4 v = *(const float4*)&g_acc[(size_t)wid * DD + lane * 4];
    float s = v.x + v.y + v.z + v.w;
    float q = v.x * v.x + v.y * v.y + v.z * v.z + v.w * v.w;
#pragma unroll
    for (int o = 16; o >= 1; o >>= 1) {
        s += __shfl_xor_sync(0xffffffffu, s, o);
        q += __shfl_xor_sync(0xffffffffu, q, o);
    }
    float mu = s * (1.f / DD);
    float var = q * (1.f / DD) - mu * mu;
    float rstd = rsqrtf(var + 1e-5f);
    float4 g = *(const float4*)&gamma[lane * 4];
    float4 b = *(const float4*)&beta[lane * 4];
    float4 o4;
    o4.x = (v.x - mu) * rstd * g.x + b.x;
    o4.y = (v.y - mu) * rstd * g.y + b.y;
    o4.z = (v.z - mu) * rstd * g.z + b.z;
    o4.w = (v.w - mu) * rstd * g.w + b.w;
    *(float4*)&out[(size_t)wid * DD + lane * 4] = o4;
}

// ---------------- launch ------------------------------------------------------------
#define GEMM_SMEM (4 * 128 * LDA * 2 + 2 * DD * 4)

extern "C" void kernel_launch(void* const* d_in, const int* in_sizes, int n_in,
                              void* d_out, int out_size) {
    const float* x       = (const float*)d_in[0];
    const int*   ei      = (const int*)d_in[1];
    const float* W       = (const float*)d_in[3];
    const float* att_src = (const float*)d_in[4];
    const float* att_dst = (const float*)d_in[5];
    const float* bias    = (const float*)d_in[6];
    const float* gate    = (const float*)d_in[7];
    const float* gamma   = (const float*)d_in[8];
    const float* beta    = (const float*)d_in[9];
    float* out = (float*)d_out;

    static bool attr_set = false;
    if (!attr_set) {
        cudaFuncSetAttribute(k_gemm, cudaFuncAttributeMaxDynamicSharedMemorySize, GEMM_SMEM);
        attr_set = true;
    }

    k_prep<<<1, DD>>>(gate, bias, out + (out_size - RR));

    int tot = NN * DD / 4 + MSEG / 4;
    k_init<<<(tot + 255) / 256, 256>>>(x);

    dim3 gg((NN + 127) / 128, RR);
    k_gemm<<<gg, 256, GEMM_SMEM>>>(x, W, att_src, att_dst);

    dim3 gh((EE / 4 + 255) / 256, RR);
    k_hist<<<gh, 256>>>(ei);
    k_scan_a<<<NSB, 256>>>();
    k_scan_b<<<1, 32>>>();
    k_scan_c<<<NSB, 256>>>();
    k_scatter<<<gh, 256>>>(ei);

    k_agg<<<(MSEG * 32 + 255) / 256, 256>>>(0);

    k_ln<<<(NN * 32 + 255) / 256, 256>>>(gamma, beta, out);
}

// round 6
// speedup vs baseline: 1.5900x; 1.5900x over previous
#include <cuda_runtime.h>
#include <cuda_fp16.h>
#include <cstdint>

#define NN 50000
#define EE 800000
#define RR 3
#define DD 128
#define HH 4
#define MSEG (RR * NN)            // 150000 segments, keyed seg = dst*RR + r
#define SCAN_BLK 1024
#define NSB ((MSEG + SCAN_BLK - 1) / SCAN_BLK)   // 147

// ---------------- scratch (device globals) --------------------------------------
__device__ __align__(16) __half g_hh[(size_t)RR * NN * DD]; // fp16 features
__device__ float g_asrc[RR * NN * HH];
__device__ float g_adst[RR * NN * HH];
__device__ float g_gw[RR];
__device__ float g_biasf[DD];
__device__ int   g_cnt[MSEG];
__device__ int   g_off[MSEG];
__device__ int   g_cur[MSEG];
__device__ int   g_bsum[256];
__device__ int   g_esrc[RR * EE];

// ---------------- packed fp32x2 helpers -----------------------------------------
#define PACK_DUP(d, f) asm("mov.b64 %0, {%1, %2};" : "=l"(d) : "f"(f), "f"(f))
#define FMA2(d, a, b, c) \
    asm("fma.rn.f32x2 %0, %1, %2, %3;" : "=l"(d) : "l"(a), "l"(b), "l"(c))

// ---------------- K0: gate softmax + fused bias ---------------------------------
__global__ void k_prep(const float* __restrict__ gate,
                       const float* __restrict__ bias,
                       float* __restrict__ out_gw) {
    __shared__ float gw[RR];
    int d = threadIdx.x;  // 128
    if (d == 0) {
        float m = gate[0];
        for (int r = 1; r < RR; r++) m = fmaxf(m, gate[r]);
        float e[RR], s = 0.f;
        for (int r = 0; r < RR; r++) { e[r] = expf(gate[r] - m); s += e[r]; }
        for (int r = 0; r < RR; r++) {
            gw[r] = e[r] / s;
            g_gw[r] = gw[r];
            out_gw[r] = gw[r];
        }
    }
    __syncthreads();
    float b = 0.f;
    for (int r = 0; r < RR; r++) b += gw[r] * bias[r * DD + d];
    g_biasf[d] = b;
}

// ---------------- K1: zero degree counts ----------------------------------------
__global__ void k_init() {
    int i = blockIdx.x * blockDim.x + threadIdx.x;
    if (i < MSEG / 4) ((int4*)g_cnt)[i] = make_int4(0, 0, 0, 0);
}

// ---------------- K2: GEMM h_r = x @ W_r (fp32x2) + fused alpha epilogue ---------
#define BM 128
#define BK 32
__global__ void __launch_bounds__(256, 2)
k_gemm(const float* __restrict__ x, const float* __restrict__ W,
       const float* __restrict__ att_src, const float* __restrict__ att_dst) {
    __shared__ float Xs[BK][BM];
    __shared__ float Ws[BK][DD];
    __shared__ float as_s[DD], ad_s[DD];

    const int r = blockIdx.y;
    const int row0 = blockIdx.x * BM;
    const int tid = threadIdx.x;
    const int tx = tid & 15;
    const int ty = tid >> 4;
    const float* Wr = W + (size_t)r * DD * DD;

    if (tid < DD) {
        as_s[tid] = __ldg(&att_src[r * DD + tid]);
        ad_s[tid] = __ldg(&att_dst[r * DD + tid]);
    }

    unsigned long long acc[4][8];
#pragma unroll
    for (int p = 0; p < 4; p++)
#pragma unroll
        for (int j = 0; j < 8; j++) acc[p][j] = 0ULL;

    const int lrow = tid >> 1;
    const int lk = (tid & 1) * 16;

    for (int k0 = 0; k0 < DD; k0 += BK) {
        const int grow = row0 + lrow;
#pragma unroll
        for (int q = 0; q < 4; q++) {
            int kk = lk + q * 4;
            float4 v = make_float4(0.f, 0.f, 0.f, 0.f);
            if (grow < NN) v = *(const float4*)&x[(size_t)grow * DD + k0 + kk];
            Xs[kk + 0][lrow] = v.x;
            Xs[kk + 1][lrow] = v.y;
            Xs[kk + 2][lrow] = v.z;
            Xs[kk + 3][lrow] = v.w;
        }
#pragma unroll
        for (int q = 0; q < 4; q++) {
            int lin = q * 1024 + tid * 4;
            *(float4*)&Ws[0][lin] = *(const float4*)&Wr[(size_t)k0 * DD + lin];
        }
        __syncthreads();

#pragma unroll 4
        for (int kk = 0; kk < BK; kk++) {
            ulonglong2 a01 = *(const ulonglong2*)&Xs[kk][ty * 8];
            ulonglong2 a23 = *(const ulonglong2*)&Xs[kk][ty * 8 + 4];
            unsigned long long av[4] = {a01.x, a01.y, a23.x, a23.y};
            float4 b0 = *(const float4*)&Ws[kk][tx * 8];
            float4 b1 = *(const float4*)&Ws[kk][tx * 8 + 4];
            float bv[8] = {b0.x, b0.y, b0.z, b0.w, b1.x, b1.y, b1.z, b1.w};
#pragma unroll
            for (int j = 0; j < 8; j++) {
                unsigned long long bb;
                PACK_DUP(bb, bv[j]);
#pragma unroll
                for (int p = 0; p < 4; p++) FMA2(acc[p][j], av[p], bb, acc[p][j]);
            }
        }
        __syncthreads();
    }

    const int head = tx >> 2;
    float asv[8], adv[8];
#pragma unroll
    for (int j = 0; j < 8; j++) {
        asv[j] = as_s[tx * 8 + j];
        adv[j] = ad_s[tx * 8 + j];
    }

#pragma unroll
    for (int p = 0; p < 4; p++) {
        int grow = row0 + ty * 8 + 2 * p;
        float lo[8], hi[8];
#pragma unroll
        for (int j = 0; j < 8; j++) {
            float2 v = *(float2*)&acc[p][j];
            lo[j] = v.x;
            hi[j] = v.y;
        }
        float psl = 0.f, pdl = 0.f, psh = 0.f, pdh = 0.f;
#pragma unroll
        for (int j = 0; j < 8; j++) {
            psl += lo[j] * asv[j];  pdl += lo[j] * adv[j];
            psh += hi[j] * asv[j];  pdh += hi[j] * adv[j];
        }
#pragma unroll
        for (int o = 1; o <= 2; o <<= 1) {
            psl += __shfl_xor_sync(0xffffffffu, psl, o);
            pdl += __shfl_xor_sync(0xffffffffu, pdl, o);
            psh += __shfl_xor_sync(0xffffffffu, psh, o);
            pdh += __shfl_xor_sync(0xffffffffu, pdh, o);
        }

        __half2 ol[4], oh[4];
#pragma unroll
        for (int j = 0; j < 4; j++) {
            ol[j] = __floats2half2_rn(lo[2 * j], lo[2 * j + 1]);
            oh[j] = __floats2half2_rn(hi[2 * j], hi[2 * j + 1]);
        }
        size_t base = ((size_t)r * NN + grow) * DD + tx * 8;
        if (grow < NN) {
            *(uint4*)&g_hh[base] = *(uint4*)ol;
            if ((tx & 3) == 0) {
                g_asrc[((size_t)r * NN + grow) * HH + head] = psl;
                g_adst[((size_t)r * NN + grow) * HH + head] = pdl;
            }
        }
        if (grow + 1 < NN) {
            *(uint4*)&g_hh[base + DD] = *(uint4*)oh;
            if ((tx & 3) == 0) {
                g_asrc[((size_t)r * NN + grow + 1) * HH + head] = psh;
                g_adst[((size_t)r * NN + grow + 1) * HH + head] = pdh;
            }
        }
    }
}

// ---------------- K4a: degree histogram (seg = dst*RR + r) -----------------------
__global__ void k_hist(const int* __restrict__ ei) {
    int e = blockIdx.x * blockDim.x + threadIdx.x;
    int r = blockIdx.y;
    if (e >= EE) return;
    int dst = __ldg(&ei[r * 2 * EE + EE + e]);
    atomicAdd(&g_cnt[dst * RR + r], 1);
}

// ---------------- K4b/c/d: scan ---------------------------------------------------
__global__ void k_scan_a() {
    __shared__ int ws[8];
    int tid = threadIdx.x;
    int base = blockIdx.x * SCAN_BLK + tid * 4;
    int s = 0;
#pragma unroll
    for (int k = 0; k < 4; k++) {
        int idx = base + k;
        if (idx < MSEG) s += g_cnt[idx];
    }
#pragma unroll
    for (int o = 16; o >= 1; o >>= 1) s += __shfl_xor_sync(0xffffffffu, s, o);
    if ((tid & 31) == 0) ws[tid >> 5] = s;
    __syncthreads();
    if (tid == 0) {
        int t = 0;
        for (int i = 0; i < 8; i++) t += ws[i];
        g_bsum[blockIdx.x] = t;
    }
}
__global__ void k_scan_b() {
    if (threadIdx.x == 0) {
        int run = 0;
        for (int i = 0; i < NSB; i++) { int v = g_bsum[i]; g_bsum[i] = run; run += v; }
    }
}
__global__ void k_scan_c() {
    __shared__ int ws[8];
    int tid = threadIdx.x;
    int lane = tid & 31, warp = tid >> 5;
    int base = blockIdx.x * SCAN_BLK + tid * 4;
    int c[4];
#pragma unroll
    for (int k = 0; k < 4; k++) {
        int idx = base + k;
        c[k] = (idx < MSEG) ? g_cnt[idx] : 0;
    }
    int t = c[0] + c[1] + c[2] + c[3];
    int inc = t;
#pragma unroll
    for (int o = 1; o < 32; o <<= 1) {
        int v = __shfl_up_sync(0xffffffffu, inc, o);
        if (lane >= o) inc += v;
    }
    if (lane == 31) ws[warp] = inc;
    __syncthreads();
    if (tid == 0) {
        int run = 0;
        for (int i = 0; i < 8; i++) { int v = ws[i]; ws[i] = run; run += v; }
    }
    __syncthreads();
    int ex = inc - t + ws[warp] + g_bsum[blockIdx.x];
#pragma unroll
    for (int k = 0; k < 4; k++) {
        int idx = base + k;
        if (idx < MSEG) { g_off[idx] = ex; g_cur[idx] = ex; }
        ex += c[k];
    }
}

// ---------------- K4e: scatter edges into CSR ------------------------------------
__global__ void k_scatter(const int* __restrict__ ei) {
    int e = blockIdx.x * blockDim.x + threadIdx.x;
    int r = blockIdx.y;
    if (e >= EE) return;
    int src = __ldg(&ei[r * 2 * EE + e]);
    int dst = __ldg(&ei[r * 2 * EE + EE + e]);
    int pos = atomicAdd(&g_cur[dst * RR + r], 1);
    g_esrc[pos] = src;
}

// ---------------- K5: fused aggregation + residual + LayerNorm (warp per dst) ----
__global__ void __launch_bounds__(256)
k_agg(const float* __restrict__ x,
      const float* __restrict__ gamma,
      const float* __restrict__ beta,
      float* __restrict__ out) {
    int dst = (blockIdx.x * blockDim.x + threadIdx.x) >> 5;
    int lane = threadIdx.x & 31;
    if (dst >= NN) return;
    int head = lane >> 3;
    int c4 = lane * 4;

    // residual + fused bias
    float4 xv = __ldg((const float4*)&x[(size_t)dst * DD + c4]);
    float4 bf = *(const float4*)&g_biasf[c4];
    float4 acc = make_float4(xv.x + bf.x, xv.y + bf.y, xv.z + bf.z, xv.w + bf.w);

#pragma unroll
    for (int r = 0; r < RR; r++) {
        int seg = dst * RR + r;
        int beg = g_off[seg];
        int end = g_cur[seg];
        if (beg == end) continue;

        float adv = g_adst[((size_t)r * NN + dst) * HH + head];
        const __half* hr = g_hh + (size_t)r * NN * DD;
        const float* ar = g_asrc + (size_t)r * NN * HH;

        float denom = 0.f;
        float4 part = make_float4(0.f, 0.f, 0.f, 0.f);
#pragma unroll 2
        for (int i = beg; i < end; i++) {
            int src = __ldg(&g_esrc[i]);
            float asv = __ldg(&ar[src * HH + head]);
            float v = asv + adv;
            v = v >= 0.f ? v : 0.2f * v;
            float w = __expf(v);
            denom += w;
            uint2 hv = __ldg((const uint2*)&hr[(size_t)src * DD + c4]);
            float2 f0 = __half22float2(*(__half2*)&hv.x);
            float2 f1 = __half22float2(*(__half2*)&hv.y);
            part.x += w * f0.x; part.y += w * f0.y;
            part.z += w * f1.x; part.w += w * f1.y;
        }
        float scale = g_gw[r] / (denom + 1e-16f);
        acc.x += scale * part.x; acc.y += scale * part.y;
        acc.z += scale * part.z; acc.w += scale * part.w;
    }

    // LayerNorm across the warp (128 values, 4 per lane)
    float s = acc.x + acc.y + acc.z + acc.w;
    float q = acc.x * acc.x + acc.y * acc.y + acc.z * acc.z + acc.w * acc.w;
#pragma unroll
    for (int o = 16; o >= 1; o >>= 1) {
        s += __shfl_xor_sync(0xffffffffu, s, o);
        q += __shfl_xor_sync(0xffffffffu, q, o);
    }
    float mu = s * (1.f / DD);
    float var = q * (1.f / DD) - mu * mu;
    float rstd = rsqrtf(var + 1e-5f);
    float4 g = __ldg((const float4*)&gamma[c4]);
    float4 b = __ldg((const float4*)&beta[c4]);
    float4 o4;
    o4.x = (acc.x - mu) * rstd * g.x + b.x;
    o4.y = (acc.y - mu) * rstd * g.y + b.y;
    o4.z = (acc.z - mu) * rstd * g.z + b.z;
    o4.w = (acc.w - mu) * rstd * g.w + b.w;
    *(float4*)&out[(size_t)dst * DD + c4] = o4;
}

// ---------------- launch ------------------------------------------------------------
extern "C" void kernel_launch(void* const* d_in, const int* in_sizes, int n_in,
                              void* d_out, int out_size) {
    const float* x       = (const float*)d_in[0];
    const int*   ei      = (const int*)d_in[1];
    const float* W       = (const float*)d_in[3];
    const float* att_src = (const float*)d_in[4];
    const float* att_dst = (const float*)d_in[5];
    const float* bias    = (const float*)d_in[6];
    const float* gate    = (const float*)d_in[7];
    const float* gamma   = (const float*)d_in[8];
    const float* beta    = (const float*)d_in[9];
    float* out = (float*)d_out;

    k_prep<<<1, DD>>>(gate, bias, out + (out_size - RR));
    k_init<<<(MSEG / 4 + 255) / 256, 256>>>();

    dim3 gg((NN + BM - 1) / BM, RR);
    k_gemm<<<gg, 256>>>(x, W, att_src, att_dst);

    dim3 gh((EE + 511) / 512, RR);
    k_hist<<<gh, 512>>>(ei);
    k_scan_a<<<NSB, 256>>>();
    k_scan_b<<<1, 32>>>();
    k_scan_c<<<NSB, 256>>>();
    k_scatter<<<gh, 512>>>(ei);

    k_agg<<<(NN * 32 + 255) / 256, 256>>>(x, gamma, beta, out);
}

// round 7
// speedup vs baseline: 1.7187x; 1.0810x over previous
#include <cuda_runtime.h>
#include <cuda_fp16.h>
#include <cstdint>

#define NN 50000
#define EE 800000
#define RR 3
#define DD 128
#define HH 4
#define MSEG (RR * NN)            // 150000 segments, keyed seg = dst*RR + r
#define SCAN_BLK 1024
#define NSB ((MSEG + SCAN_BLK - 1) / SCAN_BLK)   // 147

// ---------------- scratch (device globals) --------------------------------------
__device__ __align__(16) __half g_hh[(size_t)RR * NN * DD]; // fp16 features
__device__ float g_asrc[RR * NN * HH];
__device__ float g_adst[RR * NN * HH];
__device__ float g_gw[RR];
__device__ float g_biasf[DD];
__device__ int   g_cnt[MSEG];
__device__ int   g_off[MSEG];
__device__ int   g_cur[MSEG];
__device__ int   g_bsum[256];
__device__ int   g_esrc[RR * EE];

// ---------------- packed fp32x2 helpers -----------------------------------------
#define PACK_DUP(d, f) asm("mov.b64 %0, {%1, %2};" : "=l"(d) : "f"(f), "f"(f))
#define FMA2(d, a, b, c) \
    asm("fma.rn.f32x2 %0, %1, %2, %3;" : "=l"(d) : "l"(a), "l"(b), "l"(c))

// ---------------- K0: gate softmax + fused bias ---------------------------------
__global__ void k_prep(const float* __restrict__ gate,
                       const float* __restrict__ bias,
                       float* __restrict__ out_gw) {
    __shared__ float gw[RR];
    int d = threadIdx.x;  // 128
    if (d == 0) {
        float m = gate[0];
        for (int r = 1; r < RR; r++) m = fmaxf(m, gate[r]);
        float e[RR], s = 0.f;
        for (int r = 0; r < RR; r++) { e[r] = expf(gate[r] - m); s += e[r]; }
        for (int r = 0; r < RR; r++) {
            gw[r] = e[r] / s;
            g_gw[r] = gw[r];
            out_gw[r] = gw[r];
        }
    }
    __syncthreads();
    float b = 0.f;
    for (int r = 0; r < RR; r++) b += gw[r] * bias[r * DD + d];
    g_biasf[d] = b;
}

// ---------------- K1: zero degree counts ----------------------------------------
__global__ void k_init() {
    int i = blockIdx.x * blockDim.x + threadIdx.x;
    if (i < MSEG / 4) ((int4*)g_cnt)[i] = make_int4(0, 0, 0, 0);
}

// ---------------- K2: GEMM h_r = x @ W_r (fp32x2) + fused alpha epilogue ---------
#define BM 128
#define BK 32
__global__ void __launch_bounds__(256, 2)
k_gemm(const float* __restrict__ x, const float* __restrict__ W,
       const float* __restrict__ att_src, const float* __restrict__ att_dst) {
    __shared__ float Xs[BK][BM];
    __shared__ float Ws[BK][DD];
    __shared__ float as_s[DD], ad_s[DD];

    const int r = blockIdx.y;
    const int row0 = blockIdx.x * BM;
    const int tid = threadIdx.x;
    const int tx = tid & 15;
    const int ty = tid >> 4;
    const float* Wr = W + (size_t)r * DD * DD;

    if (tid < DD) {
        as_s[tid] = __ldg(&att_src[r * DD + tid]);
        ad_s[tid] = __ldg(&att_dst[r * DD + tid]);
    }

    unsigned long long acc[4][8];
#pragma unroll
    for (int p = 0; p < 4; p++)
#pragma unroll
        for (int j = 0; j < 8; j++) acc[p][j] = 0ULL;

    const int lrow = tid >> 1;
    const int lk = (tid & 1) * 16;

    for (int k0 = 0; k0 < DD; k0 += BK) {
        const int grow = row0 + lrow;
#pragma unroll
        for (int q = 0; q < 4; q++) {
            int kk = lk + q * 4;
            float4 v = make_float4(0.f, 0.f, 0.f, 0.f);
            if (grow < NN) v = *(const float4*)&x[(size_t)grow * DD + k0 + kk];
            Xs[kk + 0][lrow] = v.x;
            Xs[kk + 1][lrow] = v.y;
            Xs[kk + 2][lrow] = v.z;
            Xs[kk + 3][lrow] = v.w;
        }
#pragma unroll
        for (int q = 0; q < 4; q++) {
            int lin = q * 1024 + tid * 4;
            *(float4*)&Ws[0][lin] = *(const float4*)&Wr[(size_t)k0 * DD + lin];
        }
        __syncthreads();

#pragma unroll 4
        for (int kk = 0; kk < BK; kk++) {
            ulonglong2 a01 = *(const ulonglong2*)&Xs[kk][ty * 8];
            ulonglong2 a23 = *(const ulonglong2*)&Xs[kk][ty * 8 + 4];
            unsigned long long av[4] = {a01.x, a01.y, a23.x, a23.y};
            float4 b0 = *(const float4*)&Ws[kk][tx * 8];
            float4 b1 = *(const float4*)&Ws[kk][tx * 8 + 4];
            float bv[8] = {b0.x, b0.y, b0.z, b0.w, b1.x, b1.y, b1.z, b1.w};
#pragma unroll
            for (int j = 0; j < 8; j++) {
                unsigned long long bb;
                PACK_DUP(bb, bv[j]);
#pragma unroll
                for (int p = 0; p < 4; p++) FMA2(acc[p][j], av[p], bb, acc[p][j]);
            }
        }
        __syncthreads();
    }

    const int head = tx >> 2;
    float asv[8], adv[8];
#pragma unroll
    for (int j = 0; j < 8; j++) {
        asv[j] = as_s[tx * 8 + j];
        adv[j] = ad_s[tx * 8 + j];
    }

#pragma unroll
    for (int p = 0; p < 4; p++) {
        int grow = row0 + ty * 8 + 2 * p;
        float lo[8], hi[8];
#pragma unroll
        for (int j = 0; j < 8; j++) {
            float2 v = *(float2*)&acc[p][j];
            lo[j] = v.x;
            hi[j] = v.y;
        }
        float psl = 0.f, pdl = 0.f, psh = 0.f, pdh = 0.f;
#pragma unroll
        for (int j = 0; j < 8; j++) {
            psl += lo[j] * asv[j];  pdl += lo[j] * adv[j];
            psh += hi[j] * asv[j];  pdh += hi[j] * adv[j];
        }
#pragma unroll
        for (int o = 1; o <= 2; o <<= 1) {
            psl += __shfl_xor_sync(0xffffffffu, psl, o);
            pdl += __shfl_xor_sync(0xffffffffu, pdl, o);
            psh += __shfl_xor_sync(0xffffffffu, psh, o);
            pdh += __shfl_xor_sync(0xffffffffu, pdh, o);
        }

        __half2 ol[4], oh[4];
#pragma unroll
        for (int j = 0; j < 4; j++) {
            ol[j] = __floats2half2_rn(lo[2 * j], lo[2 * j + 1]);
            oh[j] = __floats2half2_rn(hi[2 * j], hi[2 * j + 1]);
        }
        size_t base = ((size_t)r * NN + grow) * DD + tx * 8;
        if (grow < NN) {
            *(uint4*)&g_hh[base] = *(uint4*)ol;
            if ((tx & 3) == 0) {
                g_asrc[((size_t)r * NN + grow) * HH + head] = psl;
                g_adst[((size_t)r * NN + grow) * HH + head] = pdl;
            }
        }
        if (grow + 1 < NN) {
            *(uint4*)&g_hh[base + DD] = *(uint4*)oh;
            if ((tx & 3) == 0) {
                g_asrc[((size_t)r * NN + grow + 1) * HH + head] = psh;
                g_adst[((size_t)r * NN + grow + 1) * HH + head] = pdh;
            }
        }
    }
}

// ---------------- K4a: degree histogram (seg = dst*RR + r) -----------------------
__global__ void k_hist(const int* __restrict__ ei) {
    int e = blockIdx.x * blockDim.x + threadIdx.x;
    int r = blockIdx.y;
    if (e >= EE) return;
    int dst = __ldg(&ei[r * 2 * EE + EE + e]);
    atomicAdd(&g_cnt[dst * RR + r], 1);
}

// ---------------- K4b/c/d: scan ---------------------------------------------------
__global__ void k_scan_a() {
    __shared__ int ws[8];
    int tid = threadIdx.x;
    int base = blockIdx.x * SCAN_BLK + tid * 4;
    int s = 0;
#pragma unroll
    for (int k = 0; k < 4; k++) {
        int idx = base + k;
        if (idx < MSEG) s += g_cnt[idx];
    }
#pragma unroll
    for (int o = 16; o >= 1; o >>= 1) s += __shfl_xor_sync(0xffffffffu, s, o);
    if ((tid & 31) == 0) ws[tid >> 5] = s;
    __syncthreads();
    if (tid == 0) {
        int t = 0;
        for (int i = 0; i < 8; i++) t += ws[i];
        g_bsum[blockIdx.x] = t;
    }
}
__global__ void k_scan_b() {
    if (threadIdx.x == 0) {
        int run = 0;
        for (int i = 0; i < NSB; i++) { int v = g_bsum[i]; g_bsum[i] = run; run += v; }
    }
}
__global__ void k_scan_c() {
    __shared__ int ws[8];
    int tid = threadIdx.x;
    int lane = tid & 31, warp = tid >> 5;
    int base = blockIdx.x * SCAN_BLK + tid * 4;
    int c[4];
#pragma unroll
    for (int k = 0; k < 4; k++) {
        int idx = base + k;
        c[k] = (idx < MSEG) ? g_cnt[idx] : 0;
    }
    int t = c[0] + c[1] + c[2] + c[3];
    int inc = t;
#pragma unroll
    for (int o = 1; o < 32; o <<= 1) {
        int v = __shfl_up_sync(0xffffffffu, inc, o);
        if (lane >= o) inc += v;
    }
    if (lane == 31) ws[warp] = inc;
    __syncthreads();
    if (tid == 0) {
        int run = 0;
        for (int i = 0; i < 8; i++) { int v = ws[i]; ws[i] = run; run += v; }
    }
    __syncthreads();
    int ex = inc - t + ws[warp] + g_bsum[blockIdx.x];
#pragma unroll
    for (int k = 0; k < 4; k++) {
        int idx = base + k;
        if (idx < MSEG) { g_off[idx] = ex; g_cur[idx] = ex; }
        ex += c[k];
    }
}

// ---------------- K4e: scatter edges into CSR ------------------------------------
__global__ void k_scatter(const int* __restrict__ ei) {
    int e = blockIdx.x * blockDim.x + threadIdx.x;
    int r = blockIdx.y;
    if (e >= EE) return;
    int src = __ldg(&ei[r * 2 * EE + e]);
    int dst = __ldg(&ei[r * 2 * EE + EE + e]);
    int pos = atomicAdd(&g_cur[dst * RR + r], 1);
    g_esrc[pos] = src;
}

// ---------------- K5: fused aggregation + residual + LayerNorm (warp per dst) ----
__global__ void __launch_bounds__(256)
k_agg(const float* __restrict__ x,
      const float* __restrict__ gamma,
      const float* __restrict__ beta,
      float* __restrict__ out) {
    int dst = (blockIdx.x * blockDim.x + threadIdx.x) >> 5;
    int lane = threadIdx.x & 31;
    if (dst >= NN) return;
    int head = lane >> 3;
    int c4 = lane * 4;

    float4 xv = __ldg((const float4*)&x[(size_t)dst * DD + c4]);
    float4 bf = *(const float4*)&g_biasf[c4];
    float4 acc = make_float4(xv.x + bf.x, xv.y + bf.y, xv.z + bf.z, xv.w + bf.w);

#pragma unroll
    for (int r = 0; r < RR; r++) {
        int seg = dst * RR + r;
        int beg = g_off[seg];
        int end = g_cur[seg];
        if (beg == end) continue;

        float adv = g_adst[((size_t)r * NN + dst) * HH + head];
        const __half* hr = g_hh + (size_t)r * NN * DD;
        const float* ar = g_asrc + (size_t)r * NN * HH;

        float denom = 0.f;
        float4 part = make_float4(0.f, 0.f, 0.f, 0.f);
#pragma unroll 4
        for (int i = beg; i < end; i++) {
            int src = __ldg(&g_esrc[i]);
            float asv = __ldg(&ar[src * HH + head]);
            float v = asv + adv;
            v = v >= 0.f ? v : 0.2f * v;
            float w = __expf(v);
            denom += w;
            uint2 hv = __ldg((const uint2*)&hr[(size_t)src * DD + c4]);
            float2 f0 = __half22float2(*(__half2*)&hv.x);
            float2 f1 = __half22float2(*(__half2*)&hv.y);
            part.x += w * f0.x; part.y += w * f0.y;
            part.z += w * f1.x; part.w += w * f1.y;
        }
        float scale = g_gw[r] / (denom + 1e-16f);
        acc.x += scale * part.x; acc.y += scale * part.y;
        acc.z += scale * part.z; acc.w += scale * part.w;
    }

    float s = acc.x + acc.y + acc.z + acc.w;
    float q = acc.x * acc.x + acc.y * acc.y + acc.z * acc.z + acc.w * acc.w;
#pragma unroll
    for (int o = 16; o >= 1; o >>= 1) {
        s += __shfl_xor_sync(0xffffffffu, s, o);
        q += __shfl_xor_sync(0xffffffffu, q, o);
    }
    float mu = s * (1.f / DD);
    float var = q * (1.f / DD) - mu * mu;
    float rstd = rsqrtf(var + 1e-5f);
    float4 g = __ldg((const float4*)&gamma[c4]);
    float4 b = __ldg((const float4*)&beta[c4]);
    float4 o4;
    o4.x = (acc.x - mu) * rstd * g.x + b.x;
    o4.y = (acc.y - mu) * rstd * g.y + b.y;
    o4.z = (acc.z - mu) * rstd * g.z + b.z;
    o4.w = (acc.w - mu) * rstd * g.w + b.w;
    *(float4*)&out[(size_t)dst * DD + c4] = o4;
}

// ---------------- launch ------------------------------------------------------------
extern "C" void kernel_launch(void* const* d_in, const int* in_sizes, int n_in,
                              void* d_out, int out_size) {
    const float* x       = (const float*)d_in[0];
    const int*   ei      = (const int*)d_in[1];
    const float* W       = (const float*)d_in[3];
    const float* att_src = (const float*)d_in[4];
    const float* att_dst = (const float*)d_in[5];
    const float* bias    = (const float*)d_in[6];
    const float* gate    = (const float*)d_in[7];
    const float* gamma   = (const float*)d_in[8];
    const float* beta    = (const float*)d_in[9];
    float* out = (float*)d_out;

    // one-time resource setup (no device memory allocation involved)
    static cudaStream_t s2 = nullptr;
    static cudaEvent_t evFork = nullptr, evJoin = nullptr;
    if (s2 == nullptr) {
        cudaStreamCreateWithFlags(&s2, cudaStreamNonBlocking);
        cudaEventCreateWithFlags(&evFork, cudaEventDisableTiming);
        cudaEventCreateWithFlags(&evJoin, cudaEventDisableTiming);
    }

    // fork: CSR-build branch runs concurrently with the GEMM branch
    cudaEventRecord(evFork, 0);
    cudaStreamWaitEvent(s2, evFork, 0);

    // ---- branch B (stream s2): CSR build (depends only on edge_index) ----
    k_init<<<(MSEG / 4 + 255) / 256, 256, 0, s2>>>();
    dim3 gh((EE + 511) / 512, RR);
    k_hist<<<gh, 512, 0, s2>>>(ei);
    k_scan_a<<<NSB, 256, 0, s2>>>();
    k_scan_b<<<1, 32, 0, s2>>>();
    k_scan_c<<<NSB, 256, 0, s2>>>();
    k_scatter<<<gh, 512, 0, s2>>>(ei);
    cudaEventRecord(evJoin, s2);

    // ---- branch A (default stream): prep + GEMM/alpha ----
    k_prep<<<1, DD>>>(gate, bias, out + (out_size - RR));
    dim3 gg((NN + BM - 1) / BM, RR);
    k_gemm<<<gg, 256>>>(x, W, att_src, att_dst);

    // join, then fused aggregation + LayerNorm
    cudaStreamWaitEvent(0, evJoin, 0);
    k_agg<<<(NN * 32 + 255) / 256, 256>>>(x, gamma, beta, out);
}

// round 8
// speedup vs baseline: 1.7222x; 1.0020x over previous
#include <cuda_runtime.h>
#include <cuda_fp16.h>
#include <cstdint>

#define NN 50000
#define EE 800000
#define RR 3
#define DD 128
#define HH 4
#define MSEG (RR * NN)            // 150000 segments, keyed seg = dst*RR + r
#define SCAN_BLK 1024
#define NSB ((MSEG + SCAN_BLK - 1) / SCAN_BLK)   // 147

// ---------------- scratch (device globals) --------------------------------------
__device__ __align__(16) __half g_hh[(size_t)RR * NN * DD]; // fp16 features
__device__ float g_asrc[RR * NN * HH];
__device__ float g_adst[RR * NN * HH];
__device__ float g_gw[RR];
__device__ float g_biasf[DD];
__device__ int   g_cnt[MSEG];
__device__ int   g_off[MSEG];
__device__ int   g_cur[MSEG];
__device__ int   g_bsum[256];
__device__ int   g_esrc[RR * EE];

// ---------------- packed fp32x2 helpers -----------------------------------------
#define PACK_DUP(d, f) asm("mov.b64 %0, {%1, %2};" : "=l"(d) : "f"(f), "f"(f))
#define FMA2(d, a, b, c) \
    asm("fma.rn.f32x2 %0, %1, %2, %3;" : "=l"(d) : "l"(a), "l"(b), "l"(c))

// ---------------- K0: gate softmax + fused bias ---------------------------------
__global__ void k_prep(const float* __restrict__ gate,
                       const float* __restrict__ bias,
                       float* __restrict__ out_gw) {
    __shared__ float gw[RR];
    int d = threadIdx.x;  // 128
    if (d == 0) {
        float m = gate[0];
        for (int r = 1; r < RR; r++) m = fmaxf(m, gate[r]);
        float e[RR], s = 0.f;
        for (int r = 0; r < RR; r++) { e[r] = expf(gate[r] - m); s += e[r]; }
        for (int r = 0; r < RR; r++) {
            gw[r] = e[r] / s;
            g_gw[r] = gw[r];
            out_gw[r] = gw[r];
        }
    }
    __syncthreads();
    float b = 0.f;
    for (int r = 0; r < RR; r++) b += gw[r] * bias[r * DD + d];
    g_biasf[d] = b;
}

// ---------------- K1: zero degree counts ----------------------------------------
__global__ void k_init() {
    int i = blockIdx.x * blockDim.x + threadIdx.x;
    if (i < MSEG / 4) ((int4*)g_cnt)[i] = make_int4(0, 0, 0, 0);
}

// ---------------- K2: GEMM h_r = x @ W_r (fp32x2) + fused alpha epilogue ---------
#define BM 128
#define BK 32
__global__ void __launch_bounds__(256, 2)
k_gemm(const float* __restrict__ x, const float* __restrict__ W,
       const float* __restrict__ att_src, const float* __restrict__ att_dst) {
    __shared__ float Xs[BK][BM];
    __shared__ float Ws[BK][DD];
    __shared__ float as_s[DD], ad_s[DD];

    const int r = blockIdx.y;
    const int row0 = blockIdx.x * BM;
    const int tid = threadIdx.x;
    const int tx = tid & 15;
    const int ty = tid >> 4;
    const float* Wr = W + (size_t)r * DD * DD;

    if (tid < DD) {
        as_s[tid] = __ldg(&att_src[r * DD + tid]);
        ad_s[tid] = __ldg(&att_dst[r * DD + tid]);
    }

    unsigned long long acc[4][8];
#pragma unroll
    for (int p = 0; p < 4; p++)
#pragma unroll
        for (int j = 0; j < 8; j++) acc[p][j] = 0ULL;

    const int lrow = tid >> 1;
    const int lk = (tid & 1) * 16;

    for (int k0 = 0; k0 < DD; k0 += BK) {
        const int grow = row0 + lrow;
#pragma unroll
        for (int q = 0; q < 4; q++) {
            int kk = lk + q * 4;
            float4 v = make_float4(0.f, 0.f, 0.f, 0.f);
            if (grow < NN) v = *(const float4*)&x[(size_t)grow * DD + k0 + kk];
            Xs[kk + 0][lrow] = v.x;
            Xs[kk + 1][lrow] = v.y;
            Xs[kk + 2][lrow] = v.z;
            Xs[kk + 3][lrow] = v.w;
        }
#pragma unroll
        for (int q = 0; q < 4; q++) {
            int lin = q * 1024 + tid * 4;
            *(float4*)&Ws[0][lin] = *(const float4*)&Wr[(size_t)k0 * DD + lin];
        }
        __syncthreads();

#pragma unroll 4
        for (int kk = 0; kk < BK; kk++) {
            ulonglong2 a01 = *(const ulonglong2*)&Xs[kk][ty * 8];
            ulonglong2 a23 = *(const ulonglong2*)&Xs[kk][ty * 8 + 4];
            unsigned long long av[4] = {a01.x, a01.y, a23.x, a23.y};
            float4 b0 = *(const float4*)&Ws[kk][tx * 8];
            float4 b1 = *(const float4*)&Ws[kk][tx * 8 + 4];
            float bv[8] = {b0.x, b0.y, b0.z, b0.w, b1.x, b1.y, b1.z, b1.w};
#pragma unroll
            for (int j = 0; j < 8; j++) {
                unsigned long long bb;
                PACK_DUP(bb, bv[j]);
#pragma unroll
                for (int p = 0; p < 4; p++) FMA2(acc[p][j], av[p], bb, acc[p][j]);
            }
        }
        __syncthreads();
    }

    const int head = tx >> 2;
    float asv[8], adv[8];
#pragma unroll
    for (int j = 0; j < 8; j++) {
        asv[j] = as_s[tx * 8 + j];
        adv[j] = ad_s[tx * 8 + j];
    }

#pragma unroll
    for (int p = 0; p < 4; p++) {
        int grow = row0 + ty * 8 + 2 * p;
        float lo[8], hi[8];
#pragma unroll
        for (int j = 0; j < 8; j++) {
            float2 v = *(float2*)&acc[p][j];
            lo[j] = v.x;
            hi[j] = v.y;
        }
        float psl = 0.f, pdl = 0.f, psh = 0.f, pdh = 0.f;
#pragma unroll
        for (int j = 0; j < 8; j++) {
            psl += lo[j] * asv[j];  pdl += lo[j] * adv[j];
            psh += hi[j] * asv[j];  pdh += hi[j] * adv[j];
        }
#pragma unroll
        for (int o = 1; o <= 2; o <<= 1) {
            psl += __shfl_xor_sync(0xffffffffu, psl, o);
            pdl += __shfl_xor_sync(0xffffffffu, pdl, o);
            psh += __shfl_xor_sync(0xffffffffu, psh, o);
            pdh += __shfl_xor_sync(0xffffffffu, pdh, o);
        }

        __half2 ol[4], oh[4];
#pragma unroll
        for (int j = 0; j < 4; j++) {
            ol[j] = __floats2half2_rn(lo[2 * j], lo[2 * j + 1]);
            oh[j] = __floats2half2_rn(hi[2 * j], hi[2 * j + 1]);
        }
        size_t base = ((size_t)r * NN + grow) * DD + tx * 8;
        if (grow < NN) {
            *(uint4*)&g_hh[base] = *(uint4*)ol;
            if ((tx & 3) == 0) {
                g_asrc[((size_t)r * NN + grow) * HH + head] = psl;
                g_adst[((size_t)r * NN + grow) * HH + head] = pdl;
            }
        }
        if (grow + 1 < NN) {
            *(uint4*)&g_hh[base + DD] = *(uint4*)oh;
            if ((tx & 3) == 0) {
                g_asrc[((size_t)r * NN + grow + 1) * HH + head] = psh;
                g_adst[((size_t)r * NN + grow + 1) * HH + head] = pdh;
            }
        }
    }
}

// ---------------- K4a: degree histogram (seg = dst*RR + r) -----------------------
__global__ void k_hist(const int* __restrict__ ei) {
    int e = blockIdx.x * blockDim.x + threadIdx.x;
    int r = blockIdx.y;
    if (e >= EE) return;
    int dst = __ldg(&ei[r * 2 * EE + EE + e]);
    atomicAdd(&g_cnt[dst * RR + r], 1);
}

// ---------------- K4b: scan stage 1 — per-block sums ------------------------------
__global__ void k_scan_a() {
    __shared__ int ws[8];
    int tid = threadIdx.x;
    int base = blockIdx.x * SCAN_BLK + tid * 4;
    int s = 0;
#pragma unroll
    for (int k = 0; k < 4; k++) {
        int idx = base + k;
        if (idx < MSEG) s += g_cnt[idx];
    }
#pragma unroll
    for (int o = 16; o >= 1; o >>= 1) s += __shfl_xor_sync(0xffffffffu, s, o);
    if ((tid & 31) == 0) ws[tid >> 5] = s;
    __syncthreads();
    if (tid == 0) {
        int t = 0;
        for (int i = 0; i < 8; i++) t += ws[i];
        g_bsum[blockIdx.x] = t;
    }
}

// ---------------- K4c: scan stage 2 — offsets (block prefix computed in-kernel) ---
__global__ void k_scan_c() {
    __shared__ int ws[8];
    __shared__ int blk_base;
    int tid = threadIdx.x;
    int lane = tid & 31, warp = tid >> 5;

    // each block reduces g_bsum[0 .. blockIdx.x) itself (replaces serial scan_b)
    {
        int s = 0;
        for (int i = tid; i < blockIdx.x; i += 256) s += g_bsum[i];
#pragma unroll
        for (int o = 16; o >= 1; o >>= 1) s += __shfl_xor_sync(0xffffffffu, s, o);
        if (lane == 0) ws[warp] = s;
        __syncthreads();
        if (tid == 0) {
            int t = 0;
            for (int i = 0; i < 8; i++) t += ws[i];
            blk_base = t;
        }
        __syncthreads();
    }

    int base = blockIdx.x * SCAN_BLK + tid * 4;
    int c[4];
#pragma unroll
    for (int k = 0; k < 4; k++) {
        int idx = base + k;
        c[k] = (idx < MSEG) ? g_cnt[idx] : 0;
    }
    int t = c[0] + c[1] + c[2] + c[3];
    int inc = t;
#pragma unroll
    for (int o = 1; o < 32; o <<= 1) {
        int v = __shfl_up_sync(0xffffffffu, inc, o);
        if (lane >= o) inc += v;
    }
    if (lane == 31) ws[warp] = inc;
    __syncthreads();
    if (tid == 0) {
        int run = 0;
        for (int i = 0; i < 8; i++) { int v = ws[i]; ws[i] = run; run += v; }
    }
    __syncthreads();
    int ex = inc - t + ws[warp] + blk_base;
#pragma unroll
    for (int k = 0; k < 4; k++) {
        int idx = base + k;
        if (idx < MSEG) { g_off[idx] = ex; g_cur[idx] = ex; }
        ex += c[k];
    }
}

// ---------------- K4e: scatter edges into CSR ------------------------------------
__global__ void k_scatter(const int* __restrict__ ei) {
    int e = blockIdx.x * blockDim.x + threadIdx.x;
    int r = blockIdx.y;
    if (e >= EE) return;
    int src = __ldg(&ei[r * 2 * EE + e]);
    int dst = __ldg(&ei[r * 2 * EE + EE + e]);
    int pos = atomicAdd(&g_cur[dst * RR + r], 1);
    g_esrc[pos] = src;
}

// ---------------- K5: fused aggregation + residual + LayerNorm (warp per dst) ----
__global__ void __launch_bounds__(256)
k_agg(const float* __restrict__ x,
      const float* __restrict__ gamma,
      const float* __restrict__ beta,
      float* __restrict__ out) {
    int dst = (blockIdx.x * blockDim.x + threadIdx.x) >> 5;
    int lane = threadIdx.x & 31;
    if (dst >= NN) return;
    int head = lane >> 3;
    int c4 = lane * 4;

    float4 xv = __ldg((const float4*)&x[(size_t)dst * DD + c4]);
    float4 bf = *(const float4*)&g_biasf[c4];
    float4 acc = make_float4(xv.x + bf.x, xv.y + bf.y, xv.z + bf.z, xv.w + bf.w);

#pragma unroll
    for (int r = 0; r < RR; r++) {
        int seg = dst * RR + r;
        int beg = g_off[seg];
        int end = g_cur[seg];
        if (beg == end) continue;

        float adv = g_adst[((size_t)r * NN + dst) * HH + head];
        const __half* hr = g_hh + (size_t)r * NN * DD;
        const float* ar = g_asrc + (size_t)r * NN * HH;

        float denom = 0.f;
        float4 part = make_float4(0.f, 0.f, 0.f, 0.f);

        int i = beg;
        // 4-wide batches: prefetch indices, then issue independent gathers
        for (; i + 4 <= end; i += 4) {
            int s0 = __ldg(&g_esrc[i]);
            int s1 = __ldg(&g_esrc[i + 1]);
            int s2 = __ldg(&g_esrc[i + 2]);
            int s3 = __ldg(&g_esrc[i + 3]);
            float a0 = __ldg(&ar[s0 * HH + head]);
            float a1 = __ldg(&ar[s1 * HH + head]);
            float a2 = __ldg(&ar[s2 * HH + head]);
            float a3 = __ldg(&ar[s3 * HH + head]);
            uint2 h0 = __ldg((const uint2*)&hr[(size_t)s0 * DD + c4]);
            uint2 h1 = __ldg((const uint2*)&hr[(size_t)s1 * DD + c4]);
            uint2 h2 = __ldg((const uint2*)&hr[(size_t)s2 * DD + c4]);
            uint2 h3 = __ldg((const uint2*)&hr[(size_t)s3 * DD + c4]);
            float va[4] = {a0 + adv, a1 + adv, a2 + adv, a3 + adv};
            uint2 hv[4] = {h0, h1, h2, h3};
#pragma unroll
            for (int q = 0; q < 4; q++) {
                float v = va[q];
                v = v >= 0.f ? v : 0.2f * v;
                float w = __expf(v);
                denom += w;
                float2 f0 = __half22float2(*(__half2*)&hv[q].x);
                float2 f1 = __half22float2(*(__half2*)&hv[q].y);
                part.x += w * f0.x; part.y += w * f0.y;
                part.z += w * f1.x; part.w += w * f1.y;
            }
        }
        for (; i < end; i++) {
            int src = __ldg(&g_esrc[i]);
            float asv = __ldg(&ar[src * HH + head]);
            float v = asv + adv;
            v = v >= 0.f ? v : 0.2f * v;
            float w = __expf(v);
            denom += w;
            uint2 hv = __ldg((const uint2*)&hr[(size_t)src * DD + c4]);
            float2 f0 = __half22float2(*(__half2*)&hv.x);
            float2 f1 = __half22float2(*(__half2*)&hv.y);
            part.x += w * f0.x; part.y += w * f0.y;
            part.z += w * f1.x; part.w += w * f1.y;
        }
        float scale = g_gw[r] / (denom + 1e-16f);
        acc.x += scale * part.x; acc.y += scale * part.y;
        acc.z += scale * part.z; acc.w += scale * part.w;
    }

    float s = acc.x + acc.y + acc.z + acc.w;
    float q = acc.x * acc.x + acc.y * acc.y + acc.z * acc.z + acc.w * acc.w;
#pragma unroll
    for (int o = 16; o >= 1; o >>= 1) {
        s += __shfl_xor_sync(0xffffffffu, s, o);
        q += __shfl_xor_sync(0xffffffffu, q, o);
    }
    float mu = s * (1.f / DD);
    float var = q * (1.f / DD) - mu * mu;
    float rstd = rsqrtf(var + 1e-5f);
    float4 g = __ldg((const float4*)&gamma[c4]);
    float4 b = __ldg((const float4*)&beta[c4]);
    float4 o4;
    o4.x = (acc.x - mu) * rstd * g.x + b.x;
    o4.y = (acc.y - mu) * rstd * g.y + b.y;
    o4.z = (acc.z - mu) * rstd * g.z + b.z;
    o4.w = (acc.w - mu) * rstd * g.w + b.w;
    *(float4*)&out[(size_t)dst * DD + c4] = o4;
}

// ---------------- launch ------------------------------------------------------------
extern "C" void kernel_launch(void* const* d_in, const int* in_sizes, int n_in,
                              void* d_out, int out_size) {
    const float* x       = (const float*)d_in[0];
    const int*   ei      = (const int*)d_in[1];
    const float* W       = (const float*)d_in[3];
    const float* att_src = (const float*)d_in[4];
    const float* att_dst = (const float*)d_in[5];
    const float* bias    = (const float*)d_in[6];
    const float* gate    = (const float*)d_in[7];
    const float* gamma   = (const float*)d_in[8];
    const float* beta    = (const float*)d_in[9];
    float* out = (float*)d_out;

    static cudaStream_t s2 = nullptr;
    static cudaEvent_t evFork = nullptr, evJoin = nullptr;
    if (s2 == nullptr) {
        cudaStreamCreateWithFlags(&s2, cudaStreamNonBlocking);
        cudaEventCreateWithFlags(&evFork, cudaEventDisableTiming);
        cudaEventCreateWithFlags(&evJoin, cudaEventDisableTiming);
    }

    // fork: CSR-build + prep branch runs concurrently with the GEMM branch
    cudaEventRecord(evFork, 0);
    cudaStreamWaitEvent(s2, evFork, 0);

    // ---- branch B (stream s2): prep + CSR build ----
    k_prep<<<1, DD, 0, s2>>>(gate, bias, out + (out_size - RR));
    k_init<<<(MSEG / 4 + 255) / 256, 256, 0, s2>>>();
    dim3 gh((EE + 511) / 512, RR);
    k_hist<<<gh, 512, 0, s2>>>(ei);
    k_scan_a<<<NSB, 256, 0, s2>>>();
    k_scan_c<<<NSB, 256, 0, s2>>>();
    k_scatter<<<gh, 512, 0, s2>>>(ei);
    cudaEventRecord(evJoin, s2);

    // ---- branch A (default stream): GEMM + fused alpha ----
    dim3 gg((NN + BM - 1) / BM, RR);
    k_gemm<<<gg, 256>>>(x, W, att_src, att_dst);

    // join, then fused aggregation + residual + LayerNorm
    cudaStreamWaitEvent(0, evJoin, 0);
    k_agg<<<(NN * 32 + 255) / 256, 256>>>(x, gamma, beta, out);
}